// round 6
// baseline (speedup 1.0000x reference)
#include <cuda_runtime.h>
#include <cuda_bf16.h>
#include <cstdint>

#define NNODE 50000
#define F 128
#define NBLK 49            // ceil(NNODE / 1024)
#define MAXE_TOT 2000000   // capacity for all 3 relations' edges
#define NF ((size_t)NNODE * F)

// Scratch (sanctioned __device__ globals)
// X slots: 0=agg_follows, 1=agg_bought_by, 2=x_user, 3=agg_buys, 4=x_item
// (matches W slot order: follows, bought_by, loop_user, buys, loop_item)
__device__ __nv_bfloat16 g_Xhi[5 * NF + 8192];
__device__ __nv_bfloat16 g_Xlo[5 * NF + 8192];
__device__ __nv_bfloat16 g_WThi[5ull * F * F];   // WT hi: [slot][n][k] = bf16(W[k][n])
__device__ __nv_bfloat16 g_WTlo[5ull * F * F];   // WT lo: residual
__device__ int g_cnt[3 * NNODE];
__device__ int g_part[3 * NNODE];
__device__ int g_off[3 * (NNODE + 1)];
__device__ int g_woff[3 * NNODE];
__device__ int g_bs[3 * NBLK];
__device__ int g_csr[MAXE_TOT];
__device__ int g_is64;

// ---------------------------------------------------------------------------
__global__ void detect_kernel(const unsigned* __restrict__ w) {
    __shared__ int nz;
    if (threadIdx.x == 0) nz = 0;
    __syncthreads();
    if (w[2 * threadIdx.x + 1] != 0) atomicOr(&nz, 1);
    __syncthreads();
    if (threadIdx.x == 0) g_is64 = (nz == 0);
}

__global__ void zero_cnt_kernel() {
    int gid = blockIdx.x * blockDim.x + threadIdx.x;
    if (gid < 3 * NNODE) g_cnt[gid] = 0;
}

// ---------------------------------------------------------------------------
__global__ void hist_kernel(const void* __restrict__ e0, const void* __restrict__ e1,
                            const void* __restrict__ e2, int E0, int E1, int E2) {
    long long gid = (long long)blockIdx.x * blockDim.x + threadIdx.x;
    const void* e; int rel; long long i; int E;
    if (gid < E0)                           { e = e0; rel = 0; i = gid;            E = E0; }
    else if (gid < (long long)E0 + E1)      { e = e1; rel = 1; i = gid - E0;       E = E1; }
    else if (gid < (long long)E0 + E1 + E2) { e = e2; rel = 2; i = gid - E0 - E1;  E = E2; }
    else return;
    long long d;
    if (g_is64) d = ((const long long*)e)[(long long)E + i];
    else        d = ((const int*)e)[E + i];
    atomicAdd(&g_cnt[rel * NNODE + (int)d], 1);
}

__global__ void scan1_kernel() {
    int rel = blockIdx.x / NBLK, blk = blockIdx.x % NBLK;
    int d = blk * 1024 + threadIdx.x;
    int v = (d < NNODE) ? g_cnt[rel * NNODE + d] : 0;
    int lane = threadIdx.x & 31, w = threadIdx.x >> 5;
    int inc = v;
#pragma unroll
    for (int o = 1; o < 32; o <<= 1) {
        int t = __shfl_up_sync(0xFFFFFFFFu, inc, o);
        if (lane >= o) inc += t;
    }
    __shared__ int wsum[32];
    if (lane == 31) wsum[w] = inc;
    __syncthreads();
    if (w == 0) {
        int t = wsum[lane];
#pragma unroll
        for (int o = 1; o < 32; o <<= 1) {
            int u = __shfl_up_sync(0xFFFFFFFFu, t, o);
            if (lane >= o) t += u;
        }
        wsum[lane] = t;
    }
    __syncthreads();
    int base = (w > 0) ? wsum[w - 1] : 0;
    if (d < NNODE) g_part[rel * NNODE + d] = base + inc - v;
    if (threadIdx.x == 1023) g_bs[rel * NBLK + blk] = base + inc;
}

__global__ void scan2_kernel() {
    int tid = threadIdx.x;
    if (tid < 3) {
        int run = 0;
        for (int b = 0; b < NBLK; b++) {
            int t = g_bs[tid * NBLK + b];
            g_bs[tid * NBLK + b] = run;
            run += t;
        }
    }
}

__global__ void scan3_kernel(int E0, int E1, int E2) {
    int gid = blockIdx.x * blockDim.x + threadIdx.x;
    if (gid >= 3 * (NNODE + 1)) return;
    int rel = gid / (NNODE + 1), d = gid - rel * (NNODE + 1);
    if (d < NNODE) {
        int o = g_part[rel * NNODE + d] + g_bs[rel * NBLK + (d >> 10)];
        g_off[gid] = o;
        g_woff[rel * NNODE + d] = o;
    } else {
        g_off[gid] = (rel == 0) ? E0 : (rel == 1) ? E1 : E2;
    }
}

__global__ void fill_kernel(const void* __restrict__ e0, const void* __restrict__ e1,
                            const void* __restrict__ e2, int E0, int E1, int E2) {
    long long gid = (long long)blockIdx.x * blockDim.x + threadIdx.x;
    const void* e; int rel; long long i; int E; int base;
    if (gid < E0)                           { e = e0; rel = 0; i = gid;           E = E0; base = 0; }
    else if (gid < (long long)E0 + E1)      { e = e1; rel = 1; i = gid - E0;      E = E1; base = E0; }
    else if (gid < (long long)E0 + E1 + E2) { e = e2; rel = 2; i = gid - E0 - E1; E = E2; base = E0 + E1; }
    else return;
    long long s, d;
    if (g_is64) {
        const long long* p = (const long long*)e;
        s = p[i]; d = p[(long long)E + i];
    } else {
        const int* p = (const int*)e;
        s = p[i]; d = p[E + i];
    }
    int pos = atomicAdd(&g_woff[rel * NNODE + (int)d], 1);
    g_csr[base + pos] = (int)s;
}

// ---------------------------------------------------------------------------
// Gather-aggregate + bf16 hi/lo split. One warp per (slot, node).
// Slots 0,1,3: CSR mean-gather. Slots 2,4: x table conversion only.
// ---------------------------------------------------------------------------
__device__ __forceinline__ void split_store(__nv_bfloat16* ph, __nv_bfloat16* pl, float4 v) {
    __nv_bfloat16 hx = __float2bfloat16(v.x), hy = __float2bfloat16(v.y);
    __nv_bfloat16 hz = __float2bfloat16(v.z), hw = __float2bfloat16(v.w);
    __nv_bfloat162 h01{hx, hy}, h23{hz, hw};
    __nv_bfloat162 l01{__float2bfloat16(v.x - __bfloat162float(hx)),
                       __float2bfloat16(v.y - __bfloat162float(hy))};
    __nv_bfloat162 l23{__float2bfloat16(v.z - __bfloat162float(hz)),
                       __float2bfloat16(v.w - __bfloat162float(hw))};
    *(__nv_bfloat162*)ph = h01;       *(__nv_bfloat162*)(ph + 2) = h23;
    *(__nv_bfloat162*)pl = l01;       *(__nv_bfloat162*)(pl + 2) = l23;
}

__global__ void __launch_bounds__(256) aggconv_kernel(
    const float* __restrict__ xu, const float* __restrict__ xi, int E0, int E1) {
    int lane = threadIdx.x & 31;
    int wid = (int)(((long long)blockIdx.x * blockDim.x + threadIdx.x) >> 5);
    if (wid >= 5 * NNODE) return;
    int slot = wid / NNODE;
    int d = wid - slot * NNODE;
    __nv_bfloat16* ph = g_Xhi + (size_t)slot * NF + (size_t)d * F + lane * 4;
    __nv_bfloat16* pl = g_Xlo + (size_t)slot * NF + (size_t)d * F + lane * 4;

    if (slot == 2 || slot == 4) {
        const float* x = (slot == 2) ? xu : xi;
        float4 v = __ldg((const float4*)(x + (size_t)d * F) + lane);
        split_store(ph, pl, v);
        return;
    }
    int rel = (slot == 0) ? 0 : (slot == 1) ? 1 : 2;
    const float* x = (rel == 1) ? xi : xu;
    const int* csr = g_csr + ((rel == 0) ? 0 : (rel == 1) ? E0 : (E0 + E1));
    int beg = g_off[rel * (NNODE + 1) + d];
    int end = g_off[rel * (NNODE + 1) + d + 1];

    float4 acc = make_float4(0.f, 0.f, 0.f, 0.f);
    int j = beg;
    for (; j + 4 <= end; j += 4) {
        int s0 = __ldg(csr + j), s1 = __ldg(csr + j + 1);
        int s2 = __ldg(csr + j + 2), s3 = __ldg(csr + j + 3);
        float4 v0 = __ldg((const float4*)(x + (size_t)s0 * F) + lane);
        float4 v1 = __ldg((const float4*)(x + (size_t)s1 * F) + lane);
        float4 v2 = __ldg((const float4*)(x + (size_t)s2 * F) + lane);
        float4 v3 = __ldg((const float4*)(x + (size_t)s3 * F) + lane);
        acc.x += (v0.x + v1.x) + (v2.x + v3.x);
        acc.y += (v0.y + v1.y) + (v2.y + v3.y);
        acc.z += (v0.z + v1.z) + (v2.z + v3.z);
        acc.w += (v0.w + v1.w) + (v2.w + v3.w);
    }
    for (; j < end; j++) {
        int s0 = __ldg(csr + j);
        float4 v0 = __ldg((const float4*)(x + (size_t)s0 * F) + lane);
        acc.x += v0.x; acc.y += v0.y; acc.z += v0.z; acc.w += v0.w;
    }
    float inv = 1.f / fmaxf((float)(end - beg), 1.f);
    acc.x *= inv; acc.y *= inv; acc.z *= inv; acc.w *= inv;
    split_store(ph, pl, acc);
}

// ---------------------------------------------------------------------------
__global__ void convW_kernel(const float* __restrict__ W0, const float* __restrict__ W1,
                             const float* __restrict__ W2, const float* __restrict__ W3,
                             const float* __restrict__ W4) {
    const float* W = (blockIdx.x == 0) ? W0 : (blockIdx.x == 1) ? W1 :
                     (blockIdx.x == 2) ? W2 : (blockIdx.x == 3) ? W3 : W4;
    __nv_bfloat16* hi = g_WThi + (size_t)blockIdx.x * F * F;
    __nv_bfloat16* lo = g_WTlo + (size_t)blockIdx.x * F * F;
    for (int idx = threadIdx.x; idx < F * F; idx += blockDim.x) {
        int k = idx >> 7, n = idx & 127;
        float v = W[idx];
        __nv_bfloat16 h = __float2bfloat16(v);
        hi[n * F + k] = h;
        lo[n * F + k] = __float2bfloat16(v - __bfloat162float(h));
    }
}

// ---------------------------------------------------------------------------
// Unified cp.async-pipelined bf16 mma GEMM for both node types.
//   user half (blocks [0, UB)):  srcs/W slots {0,1,2}, bias_u, out rows [0, N)
//   item half (blocks [UB,2UB)): srcs/W slots {3,4},   bias_i, out rows [N, 2N)
// CTA tile 128x128, 8 warps (2x4), warp 64x32, m16n8k16, 3-term hi/lo split.
// Double-buffered chunks of (source, 32-K).
// ---------------------------------------------------------------------------
#define ASTRIDE 40
#define SECT 5120                 // bf16 elems per section (128*40)
#define STAGE_ELE (4 * SECT)      // elems per stage
#define SMEM_BYTES (2 * STAGE_ELE * 2)

__device__ __forceinline__ void mma_bf16(float& c0, float& c1, float& c2, float& c3,
                                         uint32_t a0, uint32_t a1, uint32_t a2, uint32_t a3,
                                         uint32_t b0, uint32_t b1) {
    asm volatile(
        "mma.sync.aligned.m16n8k16.row.col.f32.bf16.bf16.f32 "
        "{%0,%1,%2,%3}, {%4,%5,%6,%7}, {%8,%9}, {%0,%1,%2,%3};"
        : "+f"(c0), "+f"(c1), "+f"(c2), "+f"(c3)
        : "r"(a0), "r"(a1), "r"(a2), "r"(a3), "r"(b0), "r"(b1));
}
__device__ __forceinline__ void cpa16(uint32_t d, const void* s) {
    asm volatile("cp.async.cg.shared.global [%0], [%1], 16;" :: "r"(d), "l"(s));
}
__device__ __forceinline__ void cp_commit() {
    asm volatile("cp.async.commit_group;" ::: "memory");
}
__device__ __forceinline__ void cp_wait1() {
    asm volatile("cp.async.wait_group 1;" ::: "memory");
}
__device__ __forceinline__ void cp_wait0() {
    asm volatile("cp.async.wait_group 0;" ::: "memory");
}

__global__ void __launch_bounds__(256, 2) gemm_all(
    const float* __restrict__ bias_u, const float* __restrict__ bias_i,
    float* __restrict__ out, int UB)
{
    extern __shared__ __nv_bfloat16 sm[];
    const int tid = threadIdx.x;
    const int w = tid >> 5, l = tid & 31;
    const int mBase = (w >> 2) * 64;
    const int nBase = (w & 3) * 32;
    const int lq = l >> 2;
    const int lr2 = (l & 3) * 2;

    const bool user = (int)blockIdx.x < UB;
    const int bidl = user ? blockIdx.x : blockIdx.x - UB;
    const int row0 = bidl * 128;
    const int slot0 = user ? 0 : 3;
    const int NC = user ? 12 : 8;     // nsrc*4 chunks
    const float* bias = user ? bias_u : bias_i;
    float* o = user ? out : out + NF;

    const uint32_t sb = (uint32_t)__cvta_generic_to_shared(sm);

    // stage chunk c into buffer s: 8 cp.async per thread (Ahi, Alo, Bhi, Blo)
    auto stage = [&](int s, int c) {
        const int slot = slot0 + (c >> 2);
        const int ks = (c & 3) << 5;
        const __nv_bfloat16* Ah = g_Xhi + (size_t)slot * NF;
        const __nv_bfloat16* Al = g_Xlo + (size_t)slot * NF;
        const __nv_bfloat16* Bh = g_WThi + (size_t)slot * F * F;
        const __nv_bfloat16* Bl = g_WTlo + (size_t)slot * F * F;
        const uint32_t bb = sb + s * (STAGE_ELE * 2);
#pragma unroll
        for (int t = 0; t < 2; t++) {
            int idx = t * 256 + tid;          // 0..511
            int r = idx >> 2, cc = idx & 3;   // row, 16B-chunk
            size_t go = (size_t)(row0 + r) * F + ks + cc * 8;
            uint32_t so = (uint32_t)(r * ASTRIDE + cc * 8) * 2;
            cpa16(bb + so, Ah + go);
            cpa16(bb + SECT * 2 + so, Al + go);
        }
#pragma unroll
        for (int t = 0; t < 2; t++) {
            int idx = t * 256 + tid;
            int n = idx >> 2, cc = idx & 3;
            size_t go = (size_t)n * F + ks + cc * 8;
            uint32_t so = (uint32_t)(n * ASTRIDE + cc * 8) * 2;
            cpa16(bb + SECT * 4 + so, Bh + go);
            cpa16(bb + SECT * 6 + so, Bl + go);
        }
    };

    float acc[4][4][4];
#pragma unroll
    for (int i = 0; i < 4; i++)
#pragma unroll
        for (int j = 0; j < 4; j++)
#pragma unroll
            for (int q = 0; q < 4; q++) acc[i][j][q] = 0.f;

    stage(0, 0);
    cp_commit();

    for (int c = 0; c < NC; c++) {
        if (c + 1 < NC) {
            stage((c + 1) & 1, c + 1);
            cp_commit();
            cp_wait1();
        } else {
            cp_wait0();
        }
        __syncthreads();

        const __nv_bfloat16* bb = sm + (c & 1) * STAGE_ELE;
        const __nv_bfloat16* sAhi = bb;
        const __nv_bfloat16* sAlo = bb + SECT;
        const __nv_bfloat16* sBhi = bb + 2 * SECT;
        const __nv_bfloat16* sBlo = bb + 3 * SECT;

#pragma unroll
        for (int kk = 0; kk < 32; kk += 16) {
#pragma unroll
            for (int term = 0; term < 3; term++) {
                const __nv_bfloat16* pA = (term == 1) ? sAlo : sAhi;
                const __nv_bfloat16* pB = (term == 2) ? sBlo : sBhi;
                uint32_t a[4][4], b[4][2];
#pragma unroll
                for (int i = 0; i < 4; i++) {
                    int ar = mBase + i * 16 + lq;
                    int ac = kk + lr2;
                    a[i][0] = *(const uint32_t*)&pA[ar * ASTRIDE + ac];
                    a[i][1] = *(const uint32_t*)&pA[(ar + 8) * ASTRIDE + ac];
                    a[i][2] = *(const uint32_t*)&pA[ar * ASTRIDE + ac + 8];
                    a[i][3] = *(const uint32_t*)&pA[(ar + 8) * ASTRIDE + ac + 8];
                }
#pragma unroll
                for (int j = 0; j < 4; j++) {
                    int bn = nBase + j * 8 + lq;
                    int bk = kk + lr2;
                    b[j][0] = *(const uint32_t*)&pB[bn * ASTRIDE + bk];
                    b[j][1] = *(const uint32_t*)&pB[bn * ASTRIDE + bk + 8];
                }
#pragma unroll
                for (int i = 0; i < 4; i++)
#pragma unroll
                    for (int j = 0; j < 4; j++)
                        mma_bf16(acc[i][j][0], acc[i][j][1], acc[i][j][2], acc[i][j][3],
                                 a[i][0], a[i][1], a[i][2], a[i][3], b[j][0], b[j][1]);
            }
        }
        __syncthreads();
    }

    // ---- epilogue: bias + relu + store ----
#pragma unroll
    for (int j = 0; j < 4; j++) {
        int col = nBase + j * 8 + lr2;
        float2 bv = *(const float2*)(bias + col);
#pragma unroll
        for (int i = 0; i < 4; i++) {
            int r0 = row0 + mBase + i * 16 + lq;
            int r1 = r0 + 8;
            if (r0 < NNODE) {
                float2 o0;
                o0.x = fmaxf(acc[i][j][0] + bv.x, 0.f);
                o0.y = fmaxf(acc[i][j][1] + bv.y, 0.f);
                *(float2*)(o + (size_t)r0 * F + col) = o0;
            }
            if (r1 < NNODE) {
                float2 o1;
                o1.x = fmaxf(acc[i][j][2] + bv.x, 0.f);
                o1.y = fmaxf(acc[i][j][3] + bv.y, 0.f);
                *(float2*)(o + (size_t)r1 * F + col) = o1;
            }
        }
    }
}

// ---------------------------------------------------------------------------
extern "C" void kernel_launch(void* const* d_in, const int* in_sizes, int n_in,
                              void* d_out, int out_size) {
    const float* x_user = (const float*)d_in[0];
    const float* x_item = (const float*)d_in[1];
    const void* e_follows   = d_in[2];
    const void* e_buys      = d_in[3];
    const void* e_bought_by = d_in[4];
    const float* W_follows   = (const float*)d_in[5];
    const float* W_buys      = (const float*)d_in[6];
    const float* W_bought_by = (const float*)d_in[7];
    const float* W_loop_user = (const float*)d_in[8];
    const float* b_loop_user = (const float*)d_in[9];
    const float* W_loop_item = (const float*)d_in[10];
    const float* b_loop_item = (const float*)d_in[11];

    // CSR relation order: 0=follows(u->u), 1=bought_by(i->u), 2=buys(u->i)
    int E0 = in_sizes[2] / 2;   // follows
    int E1 = in_sizes[4] / 2;   // bought_by
    int E2 = in_sizes[3] / 2;   // buys

    detect_kernel<<<1, 1024>>>((const unsigned*)e_follows);
    zero_cnt_kernel<<<(3 * NNODE + 255) / 256, 256>>>();

    long long TOT = (long long)E0 + E1 + E2;
    int eblocks = (int)((TOT + 255) / 256);
    hist_kernel<<<eblocks, 256>>>(e_follows, e_bought_by, e_buys, E0, E1, E2);
    scan1_kernel<<<3 * NBLK, 1024>>>();
    scan2_kernel<<<1, 32>>>();
    scan3_kernel<<<(3 * (NNODE + 1) + 255) / 256, 256>>>(E0, E1, E2);
    fill_kernel<<<eblocks, 256>>>(e_follows, e_bought_by, e_buys, E0, E1, E2);

    // W slots: 0=follows, 1=bought_by, 2=loop_user, 3=buys, 4=loop_item
    convW_kernel<<<5, 256>>>(W_follows, W_bought_by, W_loop_user, W_buys, W_loop_item);

    aggconv_kernel<<<(int)((5ll * NNODE * 32 + 255) / 256), 256>>>(x_user, x_item, E0, E1);

    int UB = (NNODE + 127) / 128;   // 391
    cudaFuncSetAttribute(gemm_all, cudaFuncAttributeMaxDynamicSharedMemorySize, SMEM_BYTES);
    gemm_all<<<2 * UB, 256, SMEM_BYTES>>>(b_loop_user, b_loop_item, (float*)d_out, UB);
}

// round 7
// speedup vs baseline: 1.0848x; 1.0848x over previous
#include <cuda_runtime.h>
#include <cuda_bf16.h>
#include <cstdint>

#define NNODE 50000
#define F 128
#define NBLK 49            // ceil(NNODE / 1024)
#define MAXE_TOT 2000000   // capacity for all 3 relations' edges
#define NF ((size_t)NNODE * F)

// Scratch (sanctioned __device__ globals)
__device__ float g_agg[3ull * NNODE * F];        // normalized aggregation [rel][node][feat]
__device__ __nv_bfloat16 g_WThi[5ull * F * F];   // WT hi: [slot][n][k] = bf16(W[k][n])
__device__ __nv_bfloat16 g_WTlo[5ull * F * F];   // WT lo: residual
__device__ int g_cnt[3 * NNODE];
__device__ int g_part[3 * NNODE];
__device__ int g_off[3 * (NNODE + 1)];
__device__ int g_woff[3 * NNODE];
__device__ int g_bs[3 * NBLK];
__device__ int g_csr[MAXE_TOT];
__device__ int g_is64;

// ---------------------------------------------------------------------------
__global__ void detect_kernel(const unsigned* __restrict__ w) {
    __shared__ int nz;
    if (threadIdx.x == 0) nz = 0;
    __syncthreads();
    if (w[2 * threadIdx.x + 1] != 0) atomicOr(&nz, 1);
    __syncthreads();
    if (threadIdx.x == 0) g_is64 = (nz == 0);
}

__global__ void zero_cnt_kernel() {
    int gid = blockIdx.x * blockDim.x + threadIdx.x;
    if (gid < 3 * NNODE) g_cnt[gid] = 0;
}

// ---------------------------------------------------------------------------
__global__ void hist_kernel(const void* __restrict__ e0, const void* __restrict__ e1,
                            const void* __restrict__ e2, int E0, int E1, int E2) {
    long long gid = (long long)blockIdx.x * blockDim.x + threadIdx.x;
    const void* e; int rel; long long i; int E;
    if (gid < E0)                           { e = e0; rel = 0; i = gid;            E = E0; }
    else if (gid < (long long)E0 + E1)      { e = e1; rel = 1; i = gid - E0;       E = E1; }
    else if (gid < (long long)E0 + E1 + E2) { e = e2; rel = 2; i = gid - E0 - E1;  E = E2; }
    else return;
    long long d;
    if (g_is64) d = ((const long long*)e)[(long long)E + i];
    else        d = ((const int*)e)[E + i];
    atomicAdd(&g_cnt[rel * NNODE + (int)d], 1);
}

__global__ void scan1_kernel() {
    int rel = blockIdx.x / NBLK, blk = blockIdx.x % NBLK;
    int d = blk * 1024 + threadIdx.x;
    int v = (d < NNODE) ? g_cnt[rel * NNODE + d] : 0;
    int lane = threadIdx.x & 31, w = threadIdx.x >> 5;
    int inc = v;
#pragma unroll
    for (int o = 1; o < 32; o <<= 1) {
        int t = __shfl_up_sync(0xFFFFFFFFu, inc, o);
        if (lane >= o) inc += t;
    }
    __shared__ int wsum[32];
    if (lane == 31) wsum[w] = inc;
    __syncthreads();
    if (w == 0) {
        int t = wsum[lane];
#pragma unroll
        for (int o = 1; o < 32; o <<= 1) {
            int u = __shfl_up_sync(0xFFFFFFFFu, t, o);
            if (lane >= o) t += u;
        }
        wsum[lane] = t;
    }
    __syncthreads();
    int base = (w > 0) ? wsum[w - 1] : 0;
    if (d < NNODE) g_part[rel * NNODE + d] = base + inc - v;
    if (threadIdx.x == 1023) g_bs[rel * NBLK + blk] = base + inc;
}

__global__ void scan2_kernel() {
    int tid = threadIdx.x;
    if (tid < 3) {
        int run = 0;
        for (int b = 0; b < NBLK; b++) {
            int t = g_bs[tid * NBLK + b];
            g_bs[tid * NBLK + b] = run;
            run += t;
        }
    }
}

__global__ void scan3_kernel(int E0, int E1, int E2) {
    int gid = blockIdx.x * blockDim.x + threadIdx.x;
    if (gid >= 3 * (NNODE + 1)) return;
    int rel = gid / (NNODE + 1), d = gid - rel * (NNODE + 1);
    if (d < NNODE) {
        int o = g_part[rel * NNODE + d] + g_bs[rel * NBLK + (d >> 10)];
        g_off[gid] = o;
        g_woff[rel * NNODE + d] = o;
    } else {
        g_off[gid] = (rel == 0) ? E0 : (rel == 1) ? E1 : E2;
    }
}

__global__ void fill_kernel(const void* __restrict__ e0, const void* __restrict__ e1,
                            const void* __restrict__ e2, int E0, int E1, int E2) {
    long long gid = (long long)blockIdx.x * blockDim.x + threadIdx.x;
    const void* e; int rel; long long i; int E; int base;
    if (gid < E0)                           { e = e0; rel = 0; i = gid;           E = E0; base = 0; }
    else if (gid < (long long)E0 + E1)      { e = e1; rel = 1; i = gid - E0;      E = E1; base = E0; }
    else if (gid < (long long)E0 + E1 + E2) { e = e2; rel = 2; i = gid - E0 - E1; E = E2; base = E0 + E1; }
    else return;
    long long s, d;
    if (g_is64) {
        const long long* p = (const long long*)e;
        s = p[i]; d = p[(long long)E + i];
    } else {
        const int* p = (const int*)e;
        s = p[i]; d = p[E + i];
    }
    int pos = atomicAdd(&g_woff[rel * NNODE + (int)d], 1);
    g_csr[base + pos] = (int)s;
}

// ---------------------------------------------------------------------------
// Gather-aggregate: one warp per (rel, dst). CSR mean-gather, fp32 output.
// ---------------------------------------------------------------------------
__global__ void __launch_bounds__(256) aggregate_kernel(
    const float* __restrict__ xu, const float* __restrict__ xi, int E0, int E1) {
    int lane = threadIdx.x & 31;
    int wid = (int)(((long long)blockIdx.x * blockDim.x + threadIdx.x) >> 5);
    if (wid >= 3 * NNODE) return;
    int rel = wid / NNODE;
    int beg = g_off[wid + rel];       // rel*(NNODE+1)+d == wid+rel
    int end = g_off[wid + rel + 1];
    const float* x = (rel == 1) ? xi : xu;
    const int* csr = g_csr + ((rel == 0) ? 0 : (rel == 1) ? E0 : (E0 + E1));

    float4 acc = make_float4(0.f, 0.f, 0.f, 0.f);
    int j = beg;
    for (; j + 4 <= end; j += 4) {
        int s0 = __ldg(csr + j), s1 = __ldg(csr + j + 1);
        int s2 = __ldg(csr + j + 2), s3 = __ldg(csr + j + 3);
        float4 v0 = __ldg((const float4*)(x + (size_t)s0 * F) + lane);
        float4 v1 = __ldg((const float4*)(x + (size_t)s1 * F) + lane);
        float4 v2 = __ldg((const float4*)(x + (size_t)s2 * F) + lane);
        float4 v3 = __ldg((const float4*)(x + (size_t)s3 * F) + lane);
        acc.x += (v0.x + v1.x) + (v2.x + v3.x);
        acc.y += (v0.y + v1.y) + (v2.y + v3.y);
        acc.z += (v0.z + v1.z) + (v2.z + v3.z);
        acc.w += (v0.w + v1.w) + (v2.w + v3.w);
    }
    for (; j < end; j++) {
        int s0 = __ldg(csr + j);
        float4 v0 = __ldg((const float4*)(x + (size_t)s0 * F) + lane);
        acc.x += v0.x; acc.y += v0.y; acc.z += v0.z; acc.w += v0.w;
    }
    float inv = 1.f / fmaxf((float)(end - beg), 1.f);
    acc.x *= inv; acc.y *= inv; acc.z *= inv; acc.w *= inv;
    ((float4*)(g_agg + (size_t)wid * F))[lane] = acc;
}

// ---------------------------------------------------------------------------
__global__ void convW_kernel(const float* __restrict__ W0, const float* __restrict__ W1,
                             const float* __restrict__ W2, const float* __restrict__ W3,
                             const float* __restrict__ W4) {
    const float* W = (blockIdx.x == 0) ? W0 : (blockIdx.x == 1) ? W1 :
                     (blockIdx.x == 2) ? W2 : (blockIdx.x == 3) ? W3 : W4;
    __nv_bfloat16* hi = g_WThi + (size_t)blockIdx.x * F * F;
    __nv_bfloat16* lo = g_WTlo + (size_t)blockIdx.x * F * F;
    for (int idx = threadIdx.x; idx < F * F; idx += blockDim.x) {
        int k = idx >> 7, n = idx & 127;
        float v = W[idx];
        __nv_bfloat16 h = __float2bfloat16(v);
        hi[n * F + k] = h;
        lo[n * F + k] = __float2bfloat16(v - __bfloat162float(h));
    }
}

// ---------------------------------------------------------------------------
// Fused single-launch tensor-core GEMM (bf16 3-term split, synchronous staging).
//   blocks [0, UB):   user rows — srcs {agg0, agg1, x_user}, W slots {0,1,2}
//   blocks [UB, 2UB): item rows — srcs {agg2, x_item},       W slots {3,4}
// CTA tile 128x128, 8 warps (2x4), warp 64x32, m16n8k16 atoms.
// ---------------------------------------------------------------------------
#define ASTRIDE 40

__device__ __forceinline__ void mma_bf16(float& c0, float& c1, float& c2, float& c3,
                                         uint32_t a0, uint32_t a1, uint32_t a2, uint32_t a3,
                                         uint32_t b0, uint32_t b1) {
    asm volatile(
        "mma.sync.aligned.m16n8k16.row.col.f32.bf16.bf16.f32 "
        "{%0,%1,%2,%3}, {%4,%5,%6,%7}, {%8,%9}, {%0,%1,%2,%3};"
        : "+f"(c0), "+f"(c1), "+f"(c2), "+f"(c3)
        : "r"(a0), "r"(a1), "r"(a2), "r"(a3), "r"(b0), "r"(b1));
}

__global__ void __launch_bounds__(256, 2) gemm_all(
    const float* __restrict__ xu, const float* __restrict__ xi,
    const float* __restrict__ bias_u, const float* __restrict__ bias_i,
    float* __restrict__ out, int UB)
{
    __shared__ __nv_bfloat16 sAhi[128 * ASTRIDE];
    __shared__ __nv_bfloat16 sAlo[128 * ASTRIDE];
    __shared__ __nv_bfloat16 sBhi[128 * ASTRIDE];
    __shared__ __nv_bfloat16 sBlo[128 * ASTRIDE];

    const int tid = threadIdx.x;
    const int w = tid >> 5, l = tid & 31;
    const int mBase = (w >> 2) * 64;
    const int nBase = (w & 3) * 32;
    const int lq = l >> 2;
    const int lr2 = (l & 3) * 2;

    const bool user = (int)blockIdx.x < UB;
    const int bidl = user ? blockIdx.x : blockIdx.x - UB;
    const int row0 = bidl * 128;
    const int nsrc = user ? 3 : 2;
    const float* bias = user ? bias_u : bias_i;
    float* o = user ? out : out + NF;

    float acc[4][4][4];
#pragma unroll
    for (int i = 0; i < 4; i++)
#pragma unroll
        for (int j = 0; j < 4; j++)
#pragma unroll
            for (int q = 0; q < 4; q++) acc[i][j][q] = 0.f;

    for (int s = 0; s < nsrc; s++) {
        const float* A;
        int slot;
        if (user) {
            A = (s == 0) ? g_agg : (s == 1) ? g_agg + NF : xu;
            slot = s;                       // 0=follows, 1=bought_by, 2=loop_user
        } else {
            A = (s == 0) ? g_agg + 2 * NF : xi;
            slot = 3 + s;                   // 3=buys, 4=loop_item
        }
        const __nv_bfloat16* Bh = g_WThi + (size_t)slot * F * F;
        const __nv_bfloat16* Bl = g_WTlo + (size_t)slot * F * F;

        for (int ks = 0; ks < F; ks += 32) {
            // ---- stage A chunk [128 x 32] fp32 -> hi/lo bf16 ----
#pragma unroll
            for (int t = 0; t < 4; t++) {
                int idx = t * 256 + tid;
                int r = idx >> 3, c4 = idx & 7;
                float4 v = make_float4(0.f, 0.f, 0.f, 0.f);
                int gr = row0 + r;
                if (gr < NNODE) v = __ldg((const float4*)(A + (size_t)gr * F + ks) + c4);
                __nv_bfloat16 hx = __float2bfloat16(v.x), hy = __float2bfloat16(v.y);
                __nv_bfloat16 hz = __float2bfloat16(v.z), hw = __float2bfloat16(v.w);
                __nv_bfloat162 h01{hx, hy}, h23{hz, hw};
                __nv_bfloat162 l01{__float2bfloat16(v.x - __bfloat162float(hx)),
                                   __float2bfloat16(v.y - __bfloat162float(hy))};
                __nv_bfloat162 l23{__float2bfloat16(v.z - __bfloat162float(hz)),
                                   __float2bfloat16(v.w - __bfloat162float(hw))};
                int oo = r * ASTRIDE + c4 * 4;
                *(__nv_bfloat162*)&sAhi[oo] = h01;  *(__nv_bfloat162*)&sAhi[oo + 2] = h23;
                *(__nv_bfloat162*)&sAlo[oo] = l01;  *(__nv_bfloat162*)&sAlo[oo + 2] = l23;
            }
            // ---- stage B chunk [128n x 32k] pre-split bf16 ----
#pragma unroll
            for (int t = 0; t < 4; t++) {
                int idx = t * 256 + tid;
                int n = idx >> 3, c4 = idx & 7;
                uint2 hv = *(const uint2*)(Bh + (size_t)n * F + ks + c4 * 4);
                uint2 lv = *(const uint2*)(Bl + (size_t)n * F + ks + c4 * 4);
                int oo = n * ASTRIDE + c4 * 4;
                *(uint2*)&sBhi[oo] = hv;
                *(uint2*)&sBlo[oo] = lv;
            }
            __syncthreads();

#pragma unroll
            for (int kk = 0; kk < 32; kk += 16) {
#pragma unroll
                for (int term = 0; term < 3; term++) {
                    const __nv_bfloat16* pA = (term == 1) ? sAlo : sAhi;
                    const __nv_bfloat16* pB = (term == 2) ? sBlo : sBhi;
                    uint32_t a[4][4], b[4][2];
#pragma unroll
                    for (int i = 0; i < 4; i++) {
                        int ar = mBase + i * 16 + lq;
                        int ac = kk + lr2;
                        a[i][0] = *(const uint32_t*)&pA[ar * ASTRIDE + ac];
                        a[i][1] = *(const uint32_t*)&pA[(ar + 8) * ASTRIDE + ac];
                        a[i][2] = *(const uint32_t*)&pA[ar * ASTRIDE + ac + 8];
                        a[i][3] = *(const uint32_t*)&pA[(ar + 8) * ASTRIDE + ac + 8];
                    }
#pragma unroll
                    for (int j = 0; j < 4; j++) {
                        int bn = nBase + j * 8 + lq;
                        int bk = kk + lr2;
                        b[j][0] = *(const uint32_t*)&pB[bn * ASTRIDE + bk];
                        b[j][1] = *(const uint32_t*)&pB[bn * ASTRIDE + bk + 8];
                    }
#pragma unroll
                    for (int i = 0; i < 4; i++)
#pragma unroll
                        for (int j = 0; j < 4; j++)
                            mma_bf16(acc[i][j][0], acc[i][j][1], acc[i][j][2], acc[i][j][3],
                                     a[i][0], a[i][1], a[i][2], a[i][3], b[j][0], b[j][1]);
                }
            }
            __syncthreads();
        }
    }

    // ---- epilogue: bias + relu + store ----
#pragma unroll
    for (int j = 0; j < 4; j++) {
        int col = nBase + j * 8 + lr2;
        float2 bv = *(const float2*)(bias + col);
#pragma unroll
        for (int i = 0; i < 4; i++) {
            int r0 = row0 + mBase + i * 16 + lq;
            int r1 = r0 + 8;
            if (r0 < NNODE) {
                float2 o0;
                o0.x = fmaxf(acc[i][j][0] + bv.x, 0.f);
                o0.y = fmaxf(acc[i][j][1] + bv.y, 0.f);
                *(float2*)(o + (size_t)r0 * F + col) = o0;
            }
            if (r1 < NNODE) {
                float2 o1;
                o1.x = fmaxf(acc[i][j][2] + bv.x, 0.f);
                o1.y = fmaxf(acc[i][j][3] + bv.y, 0.f);
                *(float2*)(o + (size_t)r1 * F + col) = o1;
            }
        }
    }
}

// ---------------------------------------------------------------------------
extern "C" void kernel_launch(void* const* d_in, const int* in_sizes, int n_in,
                              void* d_out, int out_size) {
    const float* x_user = (const float*)d_in[0];
    const float* x_item = (const float*)d_in[1];
    const void* e_follows   = d_in[2];
    const void* e_buys      = d_in[3];
    const void* e_bought_by = d_in[4];
    const float* W_follows   = (const float*)d_in[5];
    const float* W_buys      = (const float*)d_in[6];
    const float* W_bought_by = (const float*)d_in[7];
    const float* W_loop_user = (const float*)d_in[8];
    const float* b_loop_user = (const float*)d_in[9];
    const float* W_loop_item = (const float*)d_in[10];
    const float* b_loop_item = (const float*)d_in[11];

    // CSR relation order: 0=follows(u->u), 1=bought_by(i->u), 2=buys(u->i)
    int E0 = in_sizes[2] / 2;   // follows
    int E1 = in_sizes[4] / 2;   // bought_by
    int E2 = in_sizes[3] / 2;   // buys

    detect_kernel<<<1, 1024>>>((const unsigned*)e_follows);
    zero_cnt_kernel<<<(3 * NNODE + 255) / 256, 256>>>();

    long long TOT = (long long)E0 + E1 + E2;
    int eblocks = (int)((TOT + 255) / 256);
    hist_kernel<<<eblocks, 256>>>(e_follows, e_bought_by, e_buys, E0, E1, E2);
    scan1_kernel<<<3 * NBLK, 1024>>>();
    scan2_kernel<<<1, 32>>>();
    scan3_kernel<<<(3 * (NNODE + 1) + 255) / 256, 256>>>(E0, E1, E2);
    fill_kernel<<<eblocks, 256>>>(e_follows, e_bought_by, e_buys, E0, E1, E2);

    // W slots: 0=follows, 1=bought_by, 2=loop_user, 3=buys, 4=loop_item
    convW_kernel<<<5, 256>>>(W_follows, W_bought_by, W_loop_user, W_buys, W_loop_item);

    aggregate_kernel<<<(int)((3ll * NNODE * 32 + 255) / 256), 256>>>(x_user, x_item, E0, E1);

    int UB = (NNODE + 127) / 128;   // 391
    gemm_all<<<2 * UB, 256>>>(x_user, x_item, b_loop_user, b_loop_item,
                              (float*)d_out, UB);
}